// round 2
// baseline (speedup 1.0000x reference)
#include <cuda_runtime.h>
#include <math.h>
#include <stdint.h>

#define DIMC 512
#define IDIM 1024
#define BATCH 8
#define TLEN 1024

// ---------------- scratch (device globals; no allocation allowed) ----------------
__device__ float g_H [BATCH*DIMC*TLEN];   // conv0+gelu out   [b][d][t]
__device__ float g_Z [BATCH*TLEN*IDIM];   // join out         [b][t][i]
__device__ float g_U0[TLEN*BATCH*IDIM];   // u0 (+b_ih0+b_hh0)[t][b][j]
__device__ float g_Yr[BATCH*TLEN*IDIM];   // rnn out          [b][t][j]
__device__ float g_Y2[BATCH*TLEN*IDIM];   // u1 out           [b][t][i]
__device__ float g_Y3[BATCH*DIMC*TLEN];   // u2 out           [b][d][t]
__device__ float g_h0x[IDIM*BATCH];       // state exchange   [i][b]
__device__ float g_h1x[IDIM*BATCH];       // state exchange   [i][b]
__device__ unsigned g_count;              // barrier counter (zero-init)
__device__ volatile unsigned g_gen;       // barrier generation

__device__ __forceinline__ float gelu_f(float x) {
    return 0.5f * x * (1.0f + erff(x * 0.7071067811865476f));
}

// ---------------- depthwise conv (7 tap, pad 3) + optional gelu/residual ----------------
__global__ void dwconv_kernel(const float* __restrict__ in, const float* __restrict__ w,
                              const float* __restrict__ bias, const float* __restrict__ resid,
                              float* __restrict__ out, int do_gelu)
{
    int bd = blockIdx.x;            // b*DIMC + d
    int d  = bd % DIMC;
    __shared__ float s[TLEN + 6];
    const float* row = in + (size_t)bd * TLEN;
    for (int t = threadIdx.x; t < TLEN; t += blockDim.x) s[t + 3] = row[t];
    if (threadIdx.x < 3) { s[threadIdx.x] = 0.0f; s[TLEN + 3 + threadIdx.x] = 0.0f; }
    __syncthreads();
    float wr[7];
#pragma unroll
    for (int k = 0; k < 7; k++) wr[k] = w[d * 7 + k];
    float bb = bias[d];
    for (int t = threadIdx.x; t < TLEN; t += blockDim.x) {
        float acc = bb;
#pragma unroll
        for (int k = 0; k < 7; k++) acc += s[t + k] * wr[k];
        if (do_gelu) acc = gelu_f(acc);
        if (resid)   acc += resid[(size_t)bd * TLEN + t];
        out[(size_t)bd * TLEN + t] = acc;
    }
}

// ---------------- generic tiled SGEMM ----------------
// C[m,n] = act( sum_k A(k,m or m,k) * B[n*K+k] + bias[n] (+bias2[n]) )
// A_COL: A is [K][M] with row stride lda (col-major-like). else A is [M][K], lda=K.
// STORE_T: C[n*ldc + m] else C[m*ldc + n].   gridDim.z = batch.
#define BM 128
#define BN 64
#define BK 16

template<bool A_COL, bool DO_GELU, bool STORE_T>
__global__ __launch_bounds__(256)
void sgemm_kernel(const float* __restrict__ A, const float* __restrict__ B,
                  const float* __restrict__ bias, const float* __restrict__ bias2,
                  float* __restrict__ C,
                  int M, int N, int K, int lda,
                  long strideA, long strideC, int ldc)
{
    A += (long)blockIdx.z * strideA;
    C += (long)blockIdx.z * strideC;
    int m0 = blockIdx.y * BM;
    int n0 = blockIdx.x * BN;

    __shared__ float As[BK][BM + 4];   // row = 132 floats (528B, 16B aligned)
    __shared__ float Bs[BK][BN + 4];   // row = 68 floats  (272B, 16B aligned)

    int tid = threadIdx.x;
    int tx = tid & 15;        // n-group (0..15) -> 4 cols
    int ty = tid >> 4;        // m-group (0..15) -> 8 rows

    float acc[8][4];
#pragma unroll
    for (int i = 0; i < 8; i++)
#pragma unroll
        for (int j = 0; j < 4; j++) acc[i][j] = 0.0f;

    for (int k0 = 0; k0 < K; k0 += BK) {
        // ---- load A tile ----
        if (A_COL) {
            int kk = tid >> 4;            // 0..15
            int mm = (tid & 15) * 8;      // 0..120
            const float4* src = (const float4*)(A + (size_t)(k0 + kk) * lda + m0 + mm);
            float4 v0 = src[0], v1 = src[1];
            *(float4*)&As[kk][mm]     = v0;
            *(float4*)&As[kk][mm + 4] = v1;
        } else {
            int mm = tid >> 1;            // 0..127
            int kk = (tid & 1) * 8;       // 0 or 8
            const float4* src = (const float4*)(A + (size_t)(m0 + mm) * lda + k0 + kk);
            float4 v0 = src[0], v1 = src[1];
            As[kk + 0][mm] = v0.x; As[kk + 1][mm] = v0.y; As[kk + 2][mm] = v0.z; As[kk + 3][mm] = v0.w;
            As[kk + 4][mm] = v1.x; As[kk + 5][mm] = v1.y; As[kk + 6][mm] = v1.z; As[kk + 7][mm] = v1.w;
        }
        // ---- load B tile: B[n][k], contiguous k ----
        {
            int nn = tid >> 2;            // 0..63
            int kk = (tid & 3) * 4;       // 0,4,8,12
            float4 v = *(const float4*)(B + (size_t)(n0 + nn) * K + k0 + kk);
            Bs[kk + 0][nn] = v.x; Bs[kk + 1][nn] = v.y; Bs[kk + 2][nn] = v.z; Bs[kk + 3][nn] = v.w;
        }
        __syncthreads();

#pragma unroll
        for (int k = 0; k < BK; k++) {
            float4 a0 = *(const float4*)&As[k][ty * 8];
            float4 a1 = *(const float4*)&As[k][ty * 8 + 4];
            float4 b0 = *(const float4*)&Bs[k][tx * 4];
            float a[8] = {a0.x, a0.y, a0.z, a0.w, a1.x, a1.y, a1.z, a1.w};
            float bb[4] = {b0.x, b0.y, b0.z, b0.w};
#pragma unroll
            for (int i = 0; i < 8; i++)
#pragma unroll
                for (int j = 0; j < 4; j++) acc[i][j] += a[i] * bb[j];
        }
        __syncthreads();
    }

    // ---- epilogue ----
#pragma unroll
    for (int j = 0; j < 4; j++) {
        int n = n0 + tx * 4 + j;
        float bv = bias[n];
        if (bias2) bv += bias2[n];
#pragma unroll
        for (int i = 0; i < 8; i++) {
            int m = m0 + ty * 8 + i;
            float v = acc[i][j] + bv;
            if (DO_GELU) v = gelu_f(v);
            if (STORE_T) C[(size_t)n * ldc + m] = v;
            else         C[(size_t)m * ldc + n] = v;
        }
    }
}

// ---------------- persistent RNN kernel ----------------
#define RNN_NCTA 128
#define RNN_SMEM_FLOATS (IDIM*16 + 64 + 128)

__device__ __forceinline__ void grid_sync()
{
    __syncthreads();
    if (threadIdx.x == 0) {
        unsigned my = g_gen;
        __threadfence();
        if (atomicAdd(&g_count, 1) == gridDim.x - 1) {
            g_count = 0;
            __threadfence();
            g_gen = my + 1;
        } else {
            while (g_gen == my) __nanosleep(64);
        }
        __threadfence();
    }
    __syncthreads();
}

__global__ __launch_bounds__(256, 1)
void rnn_kernel(const float* __restrict__ U0,     // [t][b][j], includes b_ih0+b_hh0
                const float* __restrict__ Whh0,
                const float* __restrict__ Wih1,
                const float* __restrict__ Whh1,
                const float* __restrict__ bih1,
                const float* __restrict__ bhh1,
                const float* __restrict__ starter, // [2][IDIM]
                float* __restrict__ Y)             // [b][t][j]
{
    extern __shared__ float sm[];
    float* h0s   = sm;                 // [i*8+b], 8192 floats
    float* h1s   = sm + IDIM * 8;      // 8192 floats
    float* cs    = sm + IDIM * 16;     // 64 floats [r][b]
    float* wpart = cs + 64;            // 8 warps * 16

    int tid  = threadIdx.x;
    int lane = tid & 31;
    int warp = tid >> 5;
    int row0 = blockIdx.x * 8;

    // init state from starter (same for all batches)
    for (int i = tid; i < IDIM; i += 256) {
        float s0 = starter[i], s1 = starter[IDIM + i];
        float4 v0 = make_float4(s0, s0, s0, s0);
        float4 v1 = make_float4(s1, s1, s1, s1);
        ((float4*)&h0s[i * 8])[0] = v0; ((float4*)&h0s[i * 8])[1] = v0;
        ((float4*)&h1s[i * 8])[0] = v1; ((float4*)&h1s[i * 8])[1] = v1;
    }
    __syncthreads();

    // phase-A warp mapping: mat = warp&1 (0:Whh0 on h0, 1:Whh1 on h1), row pair = warp>>1
    int matA = warp & 1;
    int rpA  = warp >> 1;
    int jA   = row0 + rpA * 2;
    const float* WA  = matA ? Whh1 : Whh0;
    const float* wr0 = WA + (size_t)jA * IDIM;
    const float* wr1 = wr0 + IDIM;
    const float* hA  = matA ? h1s : h0s;

    int fr = lane >> 3, fb = lane & 7;
    float cbias = 0.0f;
    if (lane < 16 && matA == 1) cbias = bih1[jA + fr] + bhh1[jA + fr];

    // phase-B: warp = row
    int jB = row0 + warp;
    const float* wB = Wih1 + (size_t)jB * IDIM;

    for (int t = 0; t < TLEN; t++) {
        // ================= Phase A: h0_new = tanh(u0 + Whh0 h0); c = bias + Whh1 h1
        {
            float acc[16];
#pragma unroll
            for (int q = 0; q < 16; q++) acc[q] = 0.0f;
#pragma unroll 4
            for (int ii = 0; ii < IDIM; ii += 32) {
                int i = ii + lane;
                float w0 = __ldg(wr0 + i);
                float w1 = __ldg(wr1 + i);
                const float4* hp = (const float4*)(hA + i * 8);
                float4 x = hp[0], y = hp[1];
                acc[0] += w0 * x.x; acc[1] += w0 * x.y; acc[2] += w0 * x.z; acc[3] += w0 * x.w;
                acc[4] += w0 * y.x; acc[5] += w0 * y.y; acc[6] += w0 * y.z; acc[7] += w0 * y.w;
                acc[8] += w1 * x.x; acc[9] += w1 * x.y; acc[10] += w1 * x.z; acc[11] += w1 * x.w;
                acc[12] += w1 * y.x; acc[13] += w1 * y.y; acc[14] += w1 * y.z; acc[15] += w1 * y.w;
            }
#pragma unroll
            for (int q = 0; q < 16; q++) {
                acc[q] += __shfl_xor_sync(0xffffffffu, acc[q], 16);
                acc[q] += __shfl_xor_sync(0xffffffffu, acc[q], 8);
                acc[q] += __shfl_xor_sync(0xffffffffu, acc[q], 4);
                acc[q] += __shfl_xor_sync(0xffffffffu, acc[q], 2);
                acc[q] += __shfl_xor_sync(0xffffffffu, acc[q], 1);
            }
            if (lane == 0) {
#pragma unroll
                for (int q = 0; q < 16; q++) wpart[warp * 16 + q] = acc[q];
            }
            __syncwarp();
            if (lane < 16) {
                float s = wpart[warp * 16 + lane];
                int j = jA + fr;
                if (matA == 0) {
                    float v = tanhf(U0[(size_t)t * (BATCH * IDIM) + (size_t)fb * IDIM + j] + s);
                    g_h0x[j * 8 + fb] = v;
                } else {
                    cs[(rpA * 2 + fr) * 8 + fb] = cbias + s;
                }
            }
        }
        grid_sync();

        // reload full h0_new into smem (L2, bypass L1)
        {
            const float4* src = (const float4*)g_h0x;
            float4* dst = (float4*)h0s;
            for (int i = tid; i < IDIM * 8 / 4; i += 256) dst[i] = __ldcg(src + i);
        }
        __syncthreads();

        // ================= Phase B: h1_new = tanh(c + Wih1 h0_new)
        {
            float acc[8];
#pragma unroll
            for (int q = 0; q < 8; q++) acc[q] = 0.0f;
#pragma unroll 4
            for (int ii = 0; ii < IDIM; ii += 32) {
                int i = ii + lane;
                float w = __ldg(wB + i);
                const float4* hp = (const float4*)(h0s + i * 8);
                float4 x = hp[0], y = hp[1];
                acc[0] += w * x.x; acc[1] += w * x.y; acc[2] += w * x.z; acc[3] += w * x.w;
                acc[4] += w * y.x; acc[5] += w * y.y; acc[6] += w * y.z; acc[7] += w * y.w;
            }
#pragma unroll
            for (int q = 0; q < 8; q++) {
                acc[q] += __shfl_xor_sync(0xffffffffu, acc[q], 16);
                acc[q] += __shfl_xor_sync(0xffffffffu, acc[q], 8);
                acc[q] += __shfl_xor_sync(0xffffffffu, acc[q], 4);
                acc[q] += __shfl_xor_sync(0xffffffffu, acc[q], 2);
                acc[q] += __shfl_xor_sync(0xffffffffu, acc[q], 1);
            }
            if (lane == 0) {
#pragma unroll
                for (int q = 0; q < 8; q++) wpart[warp * 16 + q] = acc[q];
            }
            __syncwarp();
            if (lane < 8) {
                float v = tanhf(cs[warp * 8 + lane] + wpart[warp * 16 + lane]);
                g_h1x[jB * 8 + lane] = v;
                Y[((size_t)lane * TLEN + t) * IDIM + jB] = v;
            }
        }
        grid_sync();

        // reload full h1_new
        {
            const float4* src = (const float4*)g_h1x;
            float4* dst = (float4*)h1s;
            for (int i = tid; i < IDIM * 8 / 4; i += 256) dst[i] = __ldcg(src + i);
        }
        __syncthreads();
    }
}

// ---------------- launch ----------------
extern "C" void kernel_launch(void* const* d_in, const int* in_sizes, int n_in,
                              void* d_out, int out_size)
{
    const float* x      = (const float*)d_in[0];
    const float* w_dw0  = (const float*)d_in[1];
    const float* b_dw0  = (const float*)d_in[2];
    const float* w_dw1  = (const float*)d_in[3];
    const float* b_dw1  = (const float*)d_in[4];
    const float* w_join = (const float*)d_in[5];
    const float* b_join = (const float*)d_in[6];
    const float* w_ih0  = (const float*)d_in[7];
    const float* w_hh0  = (const float*)d_in[8];
    const float* b_ih0  = (const float*)d_in[9];
    const float* b_hh0  = (const float*)d_in[10];
    const float* w_ih1  = (const float*)d_in[11];
    const float* w_hh1  = (const float*)d_in[12];
    const float* b_ih1  = (const float*)d_in[13];
    const float* b_hh1  = (const float*)d_in[14];
    const float* w_u1   = (const float*)d_in[15];
    const float* b_u1   = (const float*)d_in[16];
    const float* w_u2   = (const float*)d_in[17];
    const float* b_u2   = (const float*)d_in[18];
    const float* starter= (const float*)d_in[19];
    float* out = (float*)d_out;

    float *H, *Z, *U0, *Yr, *Y2, *Y3;
    cudaGetSymbolAddress((void**)&H,  g_H);
    cudaGetSymbolAddress((void**)&Z,  g_Z);
    cudaGetSymbolAddress((void**)&U0, g_U0);
    cudaGetSymbolAddress((void**)&Yr, g_Yr);
    cudaGetSymbolAddress((void**)&Y2, g_Y2);
    cudaGetSymbolAddress((void**)&Y3, g_Y3);

    // 1) dwconv0 + gelu -> H [b][d][t]
    dwconv_kernel<<<BATCH * DIMC, 256>>>(x, w_dw0, b_dw0, nullptr, H, 1);

    // 2) join: Z[b][t][i] = H[b][:,t] . w_join[i,:] + b_join   (A col-major: A[k=d][m=t])
    sgemm_kernel<true, false, false><<<dim3(IDIM / BN, TLEN / BM, BATCH), 256>>>(
        H, w_join, b_join, nullptr, Z,
        TLEN, IDIM, DIMC, TLEN, (long)DIMC * TLEN, (long)TLEN * IDIM, IDIM);

    // 3) u0: U0[t][b][j] = Z[b][t][:] . w_ih0[j,:] + b_ih0 + b_hh0
    sgemm_kernel<false, false, false><<<dim3(IDIM / BN, TLEN / BM, BATCH), 256>>>(
        Z, w_ih0, b_ih0, b_hh0, U0,
        TLEN, IDIM, IDIM, IDIM, (long)TLEN * IDIM, (long)IDIM, BATCH * IDIM);

    // 4) persistent RNN over T steps -> Yr [b][t][j]
    cudaFuncSetAttribute(rnn_kernel, cudaFuncAttributeMaxDynamicSharedMemorySize,
                         RNN_SMEM_FLOATS * (int)sizeof(float));
    rnn_kernel<<<RNN_NCTA, 256, RNN_SMEM_FLOATS * (int)sizeof(float)>>>(
        U0, w_hh0, w_ih1, w_hh1, b_ih1, b_hh1, starter, Yr);

    // 5) u1 + gelu: Y2[b][t][i'] = gelu(Yr[b][t][:] . w_u1[i',:] + b_u1)
    sgemm_kernel<false, true, false><<<dim3(IDIM / BN, TLEN / BM, BATCH), 256>>>(
        Yr, w_u1, b_u1, nullptr, Y2,
        TLEN, IDIM, IDIM, IDIM, (long)TLEN * IDIM, (long)TLEN * IDIM, IDIM);

    // 6) u2 + gelu, transposed store: Y3[b][d][t]
    sgemm_kernel<false, true, true><<<dim3(DIMC / BN, TLEN / BM, BATCH), 256>>>(
        Y2, w_u2, b_u2, nullptr, Y3,
        TLEN, DIMC, IDIM, IDIM, (long)TLEN * IDIM, (long)DIMC * TLEN, TLEN);

    // 7) dwconv1 + bias + residual -> out [b][d][t]
    dwconv_kernel<<<BATCH * DIMC, 256>>>(Y3, w_dw1, b_dw1, x, out, 0);
}

// round 6
// speedup vs baseline: 1.2684x; 1.2684x over previous
#include <cuda_runtime.h>
#include <math.h>
#include <stdint.h>

#define DIMC 512
#define IDIM 1024
#define BATCH 8
#define TLEN 1024
#define NC 128            // RNN CTAs

// ---------------- scratch (device globals; no allocation allowed) ----------------
__device__ float g_H [BATCH*DIMC*TLEN];   // conv0+gelu out   [b][d][t]
__device__ float g_Z [BATCH*TLEN*IDIM];   // join out         [b][t][i]
__device__ float g_U0[TLEN*BATCH*IDIM];   // u0 (+b_ih0+b_hh0)[t][b][j]
__device__ float g_Yr[BATCH*TLEN*IDIM];   // rnn out          [b][t][j]
__device__ float g_Y2[BATCH*TLEN*IDIM];   // u1 out           [b][t][i]
__device__ float g_Y3[BATCH*DIMC*TLEN];   // u2 out           [b][d][t]
__device__ float g_h0x[BATCH*IDIM];       // state exchange   [b][i]
__device__ float g_h1x[BATCH*IDIM];       // state exchange   [b][i]
__device__ unsigned g_count;              // barrier counter (zero-init)
__device__ volatile unsigned g_gen;       // barrier generation

__device__ __forceinline__ float gelu_f(float x) {
    return 0.5f * x * (1.0f + erff(x * 0.7071067811865476f));
}

// ---------------- depthwise conv (7 tap, pad 3) + optional gelu/residual ----------------
__global__ void dwconv_kernel(const float* __restrict__ in, const float* __restrict__ w,
                              const float* __restrict__ bias, const float* __restrict__ resid,
                              float* __restrict__ out, int do_gelu)
{
    int bd = blockIdx.x;            // b*DIMC + d
    int d  = bd % DIMC;
    __shared__ float s[TLEN + 6];
    const float* row = in + (size_t)bd * TLEN;
    for (int t = threadIdx.x; t < TLEN; t += blockDim.x) s[t + 3] = row[t];
    if (threadIdx.x < 3) { s[threadIdx.x] = 0.0f; s[TLEN + 3 + threadIdx.x] = 0.0f; }
    __syncthreads();
    float wr[7];
#pragma unroll
    for (int k = 0; k < 7; k++) wr[k] = w[d * 7 + k];
    float bb = bias[d];
    for (int t = threadIdx.x; t < TLEN; t += blockDim.x) {
        float acc = bb;
#pragma unroll
        for (int k = 0; k < 7; k++) acc += s[t + k] * wr[k];
        if (do_gelu) acc = gelu_f(acc);
        if (resid)   acc += resid[(size_t)bd * TLEN + t];
        out[(size_t)bd * TLEN + t] = acc;
    }
}

// ---------------- generic tiled SGEMM (round-1 scalar version, verified) ----------------
#define BM 128
#define BN 64
#define BK 16

template<bool A_COL, bool DO_GELU, bool STORE_T>
__global__ __launch_bounds__(256)
void sgemm_kernel(const float* __restrict__ A, const float* __restrict__ B,
                  const float* __restrict__ bias, const float* __restrict__ bias2,
                  float* __restrict__ C,
                  int M, int N, int K, int lda,
                  long strideA, long strideC, int ldc)
{
    A += (long)blockIdx.z * strideA;
    C += (long)blockIdx.z * strideC;
    int m0 = blockIdx.y * BM;
    int n0 = blockIdx.x * BN;

    __shared__ float As[BK][BM + 4];
    __shared__ float Bs[BK][BN + 4];

    int tid = threadIdx.x;
    int tx = tid & 15;        // n-group (0..15) -> 4 cols
    int ty = tid >> 4;        // m-group (0..15) -> 8 rows

    float acc[8][4];
#pragma unroll
    for (int i = 0; i < 8; i++)
#pragma unroll
        for (int j = 0; j < 4; j++) acc[i][j] = 0.0f;

    for (int k0 = 0; k0 < K; k0 += BK) {
        if (A_COL) {
            int kk = tid >> 4;
            int mm = (tid & 15) * 8;
            const float4* src = (const float4*)(A + (size_t)(k0 + kk) * lda + m0 + mm);
            float4 v0 = src[0], v1 = src[1];
            *(float4*)&As[kk][mm]     = v0;
            *(float4*)&As[kk][mm + 4] = v1;
        } else {
            int mm = tid >> 1;
            int kk = (tid & 1) * 8;
            const float4* src = (const float4*)(A + (size_t)(m0 + mm) * lda + k0 + kk);
            float4 v0 = src[0], v1 = src[1];
            As[kk + 0][mm] = v0.x; As[kk + 1][mm] = v0.y; As[kk + 2][mm] = v0.z; As[kk + 3][mm] = v0.w;
            As[kk + 4][mm] = v1.x; As[kk + 5][mm] = v1.y; As[kk + 6][mm] = v1.z; As[kk + 7][mm] = v1.w;
        }
        {
            int nn = tid >> 2;
            int kk = (tid & 3) * 4;
            float4 v = *(const float4*)(B + (size_t)(n0 + nn) * K + k0 + kk);
            Bs[kk + 0][nn] = v.x; Bs[kk + 1][nn] = v.y; Bs[kk + 2][nn] = v.z; Bs[kk + 3][nn] = v.w;
        }
        __syncthreads();

#pragma unroll
        for (int k = 0; k < BK; k++) {
            float4 a0 = *(const float4*)&As[k][ty * 8];
            float4 a1 = *(const float4*)&As[k][ty * 8 + 4];
            float4 b0 = *(const float4*)&Bs[k][tx * 4];
            float a[8] = {a0.x, a0.y, a0.z, a0.w, a1.x, a1.y, a1.z, a1.w};
            float bb[4] = {b0.x, b0.y, b0.z, b0.w};
#pragma unroll
            for (int i = 0; i < 8; i++)
#pragma unroll
                for (int j = 0; j < 4; j++) acc[i][j] += a[i] * bb[j];
        }
        __syncthreads();
    }

#pragma unroll
    for (int j = 0; j < 4; j++) {
        int n = n0 + tx * 4 + j;
        float bv = bias[n];
        if (bias2) bv += bias2[n];
#pragma unroll
        for (int i = 0; i < 8; i++) {
            int m = m0 + ty * 8 + i;
            float v = acc[i][j] + bv;
            if (DO_GELU) v = gelu_f(v);
            if (STORE_T) C[(size_t)n * ldc + m] = v;
            else         C[(size_t)m * ldc + n] = v;
        }
    }
}

// ---------------- persistent RNN kernel ----------------
// smem: h0s[8192] + h1s[8192], layout [b][i] (b-major, i contiguous) + pf[256] + csm[64]
#define RNN_SMEM_FLOATS (IDIM*16 + 256 + 64)

// round-1 generation barrier (verified)
__device__ __forceinline__ void grid_sync()
{
    __syncthreads();
    if (threadIdx.x == 0) {
        unsigned my = g_gen;
        __threadfence();
        if (atomicAdd(&g_count, 1) == gridDim.x - 1) {
            g_count = 0;
            __threadfence();
            g_gen = my + 1;
        } else {
            while (g_gen == my) __nanosleep(64);
        }
        __threadfence();
    }
    __syncthreads();
}

// reduce 4x8 scalar accumulators across the warp, lane0 stores 32 floats to pf
__device__ __forceinline__ void reduce32_store(float acc[4][8], float* pfdst, int lane) {
#pragma unroll
    for (int m = 16; m >= 1; m >>= 1) {
#pragma unroll
        for (int r = 0; r < 4; r++)
#pragma unroll
            for (int b = 0; b < 8; b++)
                acc[r][b] += __shfl_xor_sync(0xffffffffu, acc[r][b], m);
    }
    if (lane == 0) {
#pragma unroll
        for (int r = 0; r < 4; r++)
#pragma unroll
            for (int b = 0; b < 8; b++)
                pfdst[r * 8 + b] = acc[r][b];
    }
}

__global__ __launch_bounds__(256, 1)
void rnn_kernel(const float* __restrict__ U0,     // [t][b][j], includes b_ih0+b_hh0
                const float* __restrict__ Whh0,
                const float* __restrict__ Wih1,
                const float* __restrict__ Whh1,
                const float* __restrict__ bih1,
                const float* __restrict__ bhh1,
                const float* __restrict__ starter, // [2][IDIM]
                float* __restrict__ Y)             // [b][t][j]
{
    extern __shared__ float sm[];
    float* h0s = sm;                    // [b][i]: b*1024 + i
    float* h1s = sm + IDIM * 8;
    float* pf  = sm + IDIM * 16;        // 8 warps * 32 floats
    float* csm = pf + 256;              // 64: layer-1 pre-acts (Whh1 part + biases)

    int tid  = threadIdx.x;
    int lane = tid & 31;
    int warp = tid >> 5;
    int row0 = blockIdx.x * 8;

    // init state from starter (broadcast across batch)
    for (int idx = tid; idx < 8192; idx += 256) {
        int i = idx & 1023;
        h0s[idx] = starter[i];
        h1s[idx] = starter[IDIM + i];
    }

    // ---- phase A mapping: warp = matA + 2*gA + 4*kcA ----
    int matA = warp & 1;
    int gA   = (warp >> 1) & 1;
    int kcA  = warp >> 2;
    const float* WA = matA ? Whh1 : Whh0;
    float* hA = matA ? h1s : h0s;
    int kbA = kcA * 512;
    // preload phase-A weights into registers: 4 grps x 4 rows x float4
    float4 wAreg[4][4];
#pragma unroll
    for (int grp = 0; grp < 4; grp++)
#pragma unroll
        for (int r = 0; r < 4; r++)
            wAreg[grp][r] = *(const float4*)&WA[(size_t)(row0 + gA * 4 + r) * IDIM
                                                + kbA + grp * 128 + lane * 4];

    // ---- phase B mapping: warp = gB + 2*kcB ----
    int gB  = warp & 1;
    int kcB = warp >> 1;
    int kbB = kcB * 256;
    float4 wBreg[2][4];
#pragma unroll
    for (int grp = 0; grp < 2; grp++)
#pragma unroll
        for (int r = 0; r < 4; r++)
            wBreg[grp][r] = *(const float4*)&Wih1[(size_t)(row0 + gB * 4 + r) * IDIM
                                                  + kbB + grp * 128 + lane * 4];

    // combine-thread params (phase A, tid<128): m = tid>>6
    int cmbA_b = tid & 7;
    int cmbA_r = (tid >> 3) & 3;
    int cmbA_g = (tid >> 5) & 1;
    int cmbA_j = row0 + cmbA_g * 4 + cmbA_r;
    float cbias = 0.0f;
    if (tid >= 64 && tid < 128) cbias = bih1[cmbA_j] + bhh1[cmbA_j];
    // combine-thread params (phase B, tid<64)
    int cmbB_b = tid & 7;
    int cmbB_r = tid >> 3;
    int cmbB_j = row0 + cmbB_r;

    __syncthreads();

    for (int t = 0; t < TLEN; t++) {
        // prefetch U0 for this CTA's h0 rows (hidden under phase-A dot)
        float u0v = 0.0f;
        if (tid < 64)
            u0v = __ldcg(&U0[(size_t)t * (BATCH * IDIM) + (size_t)cmbA_b * IDIM + cmbA_j]);

        // ---------- Phase A dot: 4 rows x 8 batch over K-chunk 512 ----------
        {
            float acc[4][8];
#pragma unroll
            for (int r = 0; r < 4; r++)
#pragma unroll
                for (int b = 0; b < 8; b++) acc[r][b] = 0.0f;
#pragma unroll
            for (int grp = 0; grp < 4; grp++) {
                int ib = kbA + grp * 128 + lane * 4;
                float4 h[8];
#pragma unroll
                for (int b = 0; b < 8; b++) h[b] = *(const float4*)&hA[b * 1024 + ib];
#pragma unroll
                for (int r = 0; r < 4; r++) {
                    float4 wv = wAreg[grp][r];
#pragma unroll
                    for (int b = 0; b < 8; b++) {
                        acc[r][b] += wv.x * h[b].x;
                        acc[r][b] += wv.y * h[b].y;
                        acc[r][b] += wv.z * h[b].z;
                        acc[r][b] += wv.w * h[b].w;
                    }
                }
            }
            reduce32_store(acc, &pf[warp * 32], lane);
        }
        __syncthreads();

        // ---------- Phase A combine ----------
        if (tid < 128) {
            int m = tid >> 6;
            int w1 = m + 2 * cmbA_g;
            int fidx = cmbA_r * 8 + cmbA_b;
            float s = pf[w1 * 32 + fidx] + pf[(w1 + 4) * 32 + fidx];
            if (m == 0) {
                float hv = tanhf(u0v + s);
                g_h0x[cmbA_b * IDIM + cmbA_j] = hv;
            } else {
                csm[(cmbA_g * 4 + cmbA_r) * 8 + cmbA_b] = cbias + s;
            }
        }
        grid_sync();

        // ---------- h0 broadcast ----------
        for (int v = tid; v < 2048; v += 256)
            ((float4*)h0s)[v] = __ldcg((const float4*)g_h0x + v);
        __syncthreads();

        // ---------- Phase B dot: 4 rows x 8 batch over K-chunk 256 ----------
        {
            float acc[4][8];
#pragma unroll
            for (int r = 0; r < 4; r++)
#pragma unroll
                for (int b = 0; b < 8; b++) acc[r][b] = 0.0f;
#pragma unroll
            for (int grp = 0; grp < 2; grp++) {
                int ib = kbB + grp * 128 + lane * 4;
                float4 h[8];
#pragma unroll
                for (int b = 0; b < 8; b++) h[b] = *(const float4*)&h0s[b * 1024 + ib];
#pragma unroll
                for (int r = 0; r < 4; r++) {
                    float4 wv = wBreg[grp][r];
#pragma unroll
                    for (int b = 0; b < 8; b++) {
                        acc[r][b] += wv.x * h[b].x;
                        acc[r][b] += wv.y * h[b].y;
                        acc[r][b] += wv.z * h[b].z;
                        acc[r][b] += wv.w * h[b].w;
                    }
                }
            }
            reduce32_store(acc, &pf[warp * 32], lane);
        }
        __syncthreads();

        // ---------- Phase B combine ----------
        if (tid < 64) {
            int gg = cmbB_r >> 2;
            int fidx = (cmbB_r & 3) * 8 + cmbB_b;
            float s = pf[(gg + 0) * 32 + fidx] + pf[(gg + 2) * 32 + fidx]
                    + pf[(gg + 4) * 32 + fidx] + pf[(gg + 6) * 32 + fidx];
            float hv = tanhf(csm[cmbB_r * 8 + cmbB_b] + s);
            g_h1x[cmbB_b * IDIM + cmbB_j] = hv;
            Y[((size_t)cmbB_b * TLEN + t) * IDIM + cmbB_j] = hv;
        }
        grid_sync();

        // ---------- h1 broadcast ----------
        for (int v = tid; v < 2048; v += 256)
            ((float4*)h1s)[v] = __ldcg((const float4*)g_h1x + v);
        __syncthreads();
    }
}

// ---------------- launch ----------------
extern "C" void kernel_launch(void* const* d_in, const int* in_sizes, int n_in,
                              void* d_out, int out_size)
{
    const float* x      = (const float*)d_in[0];
    const float* w_dw0  = (const float*)d_in[1];
    const float* b_dw0  = (const float*)d_in[2];
    const float* w_dw1  = (const float*)d_in[3];
    const float* b_dw1  = (const float*)d_in[4];
    const float* w_join = (const float*)d_in[5];
    const float* b_join = (const float*)d_in[6];
    const float* w_ih0  = (const float*)d_in[7];
    const float* w_hh0  = (const float*)d_in[8];
    const float* b_ih0  = (const float*)d_in[9];
    const float* b_hh0  = (const float*)d_in[10];
    const float* w_ih1  = (const float*)d_in[11];
    const float* w_hh1  = (const float*)d_in[12];
    const float* b_ih1  = (const float*)d_in[13];
    const float* b_hh1  = (const float*)d_in[14];
    const float* w_u1   = (const float*)d_in[15];
    const float* b_u1   = (const float*)d_in[16];
    const float* w_u2   = (const float*)d_in[17];
    const float* b_u2   = (const float*)d_in[18];
    const float* starter= (const float*)d_in[19];
    float* out = (float*)d_out;

    float *H, *Z, *U0, *Yr, *Y2, *Y3;
    cudaGetSymbolAddress((void**)&H,  g_H);
    cudaGetSymbolAddress((void**)&Z,  g_Z);
    cudaGetSymbolAddress((void**)&U0, g_U0);
    cudaGetSymbolAddress((void**)&Yr, g_Yr);
    cudaGetSymbolAddress((void**)&Y2, g_Y2);
    cudaGetSymbolAddress((void**)&Y3, g_Y3);

    // 1) dwconv0 + gelu -> H [b][d][t]
    dwconv_kernel<<<BATCH * DIMC, 256>>>(x, w_dw0, b_dw0, nullptr, H, 1);

    // 2) join: Z[b][t][i] = H[b][:,t] . w_join[i,:] + b_join
    sgemm_kernel<true, false, false><<<dim3(IDIM / BN, TLEN / BM, BATCH), 256>>>(
        H, w_join, b_join, nullptr, Z,
        TLEN, IDIM, DIMC, TLEN, (long)DIMC * TLEN, (long)TLEN * IDIM, IDIM);

    // 3) u0: U0[t][b][j] = Z[b][t][:] . w_ih0[j,:] + b_ih0 + b_hh0
    sgemm_kernel<false, false, false><<<dim3(IDIM / BN, TLEN / BM, BATCH), 256>>>(
        Z, w_ih0, b_ih0, b_hh0, U0,
        TLEN, IDIM, IDIM, IDIM, (long)TLEN * IDIM, (long)IDIM, BATCH * IDIM);

    // 4) persistent RNN over T steps -> Yr [b][t][j]
    cudaFuncSetAttribute(rnn_kernel, cudaFuncAttributeMaxDynamicSharedMemorySize,
                         RNN_SMEM_FLOATS * (int)sizeof(float));
    rnn_kernel<<<NC, 256, RNN_SMEM_FLOATS * (int)sizeof(float)>>>(
        U0, w_hh0, w_ih1, w_hh1, b_ih1, b_hh1, starter, Yr);

    // 5) u1 + gelu
    sgemm_kernel<false, true, false><<<dim3(IDIM / BN, TLEN / BM, BATCH), 256>>>(
        Yr, w_u1, b_u1, nullptr, Y2,
        TLEN, IDIM, IDIM, IDIM, (long)TLEN * IDIM, (long)TLEN * IDIM, IDIM);

    // 6) u2 + gelu, transposed store: Y3[b][d][t]
    sgemm_kernel<false, true, true><<<dim3(DIMC / BN, TLEN / BM, BATCH), 256>>>(
        Y2, w_u2, b_u2, nullptr, Y3,
        TLEN, DIMC, IDIM, IDIM, (long)TLEN * IDIM, (long)DIMC * TLEN, TLEN);

    // 7) dwconv1 + bias + residual -> out [b][d][t]
    dwconv_kernel<<<BATCH * DIMC, 256>>>(Y3, w_dw1, b_dw1, x, out, 0);
}

// round 7
// speedup vs baseline: 1.7012x; 1.3412x over previous
#include <cuda_runtime.h>
#include <math.h>
#include <stdint.h>

#define DIMC 512
#define IDIM 1024
#define BATCH 8
#define TLEN 1024
#define NC 128            // RNN CTAs (8 leaves x 16)

// ---------------- scratch (device globals; no allocation allowed) ----------------
__device__ float g_H [BATCH*DIMC*TLEN];   // conv0+gelu out   [b][d][t]
__device__ float g_Z [BATCH*TLEN*IDIM];   // join out         [b][t][i]
__device__ float g_U0[TLEN*BATCH*IDIM];   // u0 (+b_ih0+b_hh0)[t][b][j]
__device__ float g_Yr[BATCH*TLEN*IDIM];   // rnn out          [b][t][j]
__device__ float g_Y2[BATCH*TLEN*IDIM];   // u1 out           [b][t][i]
__device__ float g_Y3[BATCH*DIMC*TLEN];   // u2 out           [b][d][t]
__device__ float g_h0x[2][BATCH*IDIM];    // h0 exchange, double buffered [b][i]
__device__ float g_h1x[2][BATCH*IDIM];    // h1 exchange, double buffered [b][i]
__device__ unsigned g_l1[8*64];           // tree-barrier leaf counters (256B apart)
__device__ unsigned g_root;               // tree-barrier root counter
__device__ volatile unsigned g_gen2;      // completed-epoch generation (monotonic)

__device__ __forceinline__ float gelu_f(float x) {
    return 0.5f * x * (1.0f + erff(x * 0.7071067811865476f));
}

// ---------------- barrier counter reset (graph replays reuse device globals) -----
__global__ void zero_tree_kernel() {
    int i = threadIdx.x;
    if (i < 8 * 64) g_l1[i] = 0;
    if (i == 0) { g_root = 0; g_gen2 = 0; }
}

// ---------------- depthwise conv (7 tap, pad 3) + optional gelu/residual ----------------
__global__ void dwconv_kernel(const float* __restrict__ in, const float* __restrict__ w,
                              const float* __restrict__ bias, const float* __restrict__ resid,
                              float* __restrict__ out, int do_gelu)
{
    int bd = blockIdx.x;            // b*DIMC + d
    int d  = bd % DIMC;
    __shared__ float s[TLEN + 6];
    const float* row = in + (size_t)bd * TLEN;
    for (int t = threadIdx.x; t < TLEN; t += blockDim.x) s[t + 3] = row[t];
    if (threadIdx.x < 3) { s[threadIdx.x] = 0.0f; s[TLEN + 3 + threadIdx.x] = 0.0f; }
    __syncthreads();
    float wr[7];
#pragma unroll
    for (int k = 0; k < 7; k++) wr[k] = w[d * 7 + k];
    float bb = bias[d];
    for (int t = threadIdx.x; t < TLEN; t += blockDim.x) {
        float acc = bb;
#pragma unroll
        for (int k = 0; k < 7; k++) acc += s[t + k] * wr[k];
        if (do_gelu) acc = gelu_f(acc);
        if (resid)   acc += resid[(size_t)bd * TLEN + t];
        out[(size_t)bd * TLEN + t] = acc;
    }
}

// ---------------- generic tiled SGEMM (round-1 scalar version, verified) ----------------
#define BM 128
#define BN 64
#define BK 16

template<bool A_COL, bool DO_GELU, bool STORE_T>
__global__ __launch_bounds__(256)
void sgemm_kernel(const float* __restrict__ A, const float* __restrict__ B,
                  const float* __restrict__ bias, const float* __restrict__ bias2,
                  float* __restrict__ C,
                  int M, int N, int K, int lda,
                  long strideA, long strideC, int ldc)
{
    A += (long)blockIdx.z * strideA;
    C += (long)blockIdx.z * strideC;
    int m0 = blockIdx.y * BM;
    int n0 = blockIdx.x * BN;

    __shared__ float As[BK][BM + 4];
    __shared__ float Bs[BK][BN + 4];

    int tid = threadIdx.x;
    int tx = tid & 15;        // n-group (0..15) -> 4 cols
    int ty = tid >> 4;        // m-group (0..15) -> 8 rows

    float acc[8][4];
#pragma unroll
    for (int i = 0; i < 8; i++)
#pragma unroll
        for (int j = 0; j < 4; j++) acc[i][j] = 0.0f;

    for (int k0 = 0; k0 < K; k0 += BK) {
        if (A_COL) {
            int kk = tid >> 4;
            int mm = (tid & 15) * 8;
            const float4* src = (const float4*)(A + (size_t)(k0 + kk) * lda + m0 + mm);
            float4 v0 = src[0], v1 = src[1];
            *(float4*)&As[kk][mm]     = v0;
            *(float4*)&As[kk][mm + 4] = v1;
        } else {
            int mm = tid >> 1;
            int kk = (tid & 1) * 8;
            const float4* src = (const float4*)(A + (size_t)(m0 + mm) * lda + k0 + kk);
            float4 v0 = src[0], v1 = src[1];
            As[kk + 0][mm] = v0.x; As[kk + 1][mm] = v0.y; As[kk + 2][mm] = v0.z; As[kk + 3][mm] = v0.w;
            As[kk + 4][mm] = v1.x; As[kk + 5][mm] = v1.y; As[kk + 6][mm] = v1.z; As[kk + 7][mm] = v1.w;
        }
        {
            int nn = tid >> 2;
            int kk = (tid & 3) * 4;
            float4 v = *(const float4*)(B + (size_t)(n0 + nn) * K + k0 + kk);
            Bs[kk + 0][nn] = v.x; Bs[kk + 1][nn] = v.y; Bs[kk + 2][nn] = v.z; Bs[kk + 3][nn] = v.w;
        }
        __syncthreads();

#pragma unroll
        for (int k = 0; k < BK; k++) {
            float4 a0 = *(const float4*)&As[k][ty * 8];
            float4 a1 = *(const float4*)&As[k][ty * 8 + 4];
            float4 b0 = *(const float4*)&Bs[k][tx * 4];
            float a[8] = {a0.x, a0.y, a0.z, a0.w, a1.x, a1.y, a1.z, a1.w};
            float bb[4] = {b0.x, b0.y, b0.z, b0.w};
#pragma unroll
            for (int i = 0; i < 8; i++)
#pragma unroll
                for (int j = 0; j < 4; j++) acc[i][j] += a[i] * bb[j];
        }
        __syncthreads();
    }

#pragma unroll
    for (int j = 0; j < 4; j++) {
        int n = n0 + tx * 4 + j;
        float bv = bias[n];
        if (bias2) bv += bias2[n];
#pragma unroll
        for (int i = 0; i < 8; i++) {
            int m = m0 + ty * 8 + i;
            float v = acc[i][j] + bv;
            if (DO_GELU) v = gelu_f(v);
            if (STORE_T) C[(size_t)n * ldc + m] = v;
            else         C[(size_t)m * ldc + n] = v;
        }
    }
}

// ---------------- persistent RNN kernel: pipelined single-sync-per-slot ----------------
// smem: h0s[8192] + h1s[8192] ([b][i]) + pf[512] (A: warps 0..7 at 0, B: warps 0..7 at 256)
#define RNN_SMEM_FLOATS (IDIM*16 + 512)

// tree barrier, monotonic counters, epoch e >= 1
__device__ __forceinline__ void tree_sync(unsigned e)
{
    __syncthreads();
    if (threadIdx.x == 0) {
        __threadfence();
        unsigned grp = blockIdx.x & 7;               // 16 CTAs per leaf
        if (atomicAdd(&g_l1[grp * 64], 1u) == 16u * e - 1u) {
            if (atomicAdd(&g_root, 1u) == 8u * e - 1u) {
                __threadfence();
                g_gen2 = e;
            }
        }
        while (g_gen2 < e) { }
        __threadfence();
    }
    __syncthreads();
}

// reduce 4x8 scalar accumulators across the warp, lane0 stores 32 floats to pfdst
__device__ __forceinline__ void reduce32_store(float acc[4][8], float* pfdst, int lane) {
#pragma unroll
    for (int m = 16; m >= 1; m >>= 1) {
#pragma unroll
        for (int r = 0; r < 4; r++)
#pragma unroll
            for (int b = 0; b < 8; b++)
                acc[r][b] += __shfl_xor_sync(0xffffffffu, acc[r][b], m);
    }
    if (lane == 0) {
#pragma unroll
        for (int r = 0; r < 4; r++)
#pragma unroll
            for (int b = 0; b < 8; b++)
                pfdst[r * 8 + b] = acc[r][b];
    }
}

__global__ __launch_bounds__(256, 1)
void rnn_kernel(const float* __restrict__ U0,     // [t][b][j], includes b_ih0+b_hh0
                const float* __restrict__ Whh0,
                const float* __restrict__ Wih1,
                const float* __restrict__ Whh1,
                const float* __restrict__ bih1,
                const float* __restrict__ bhh1,
                const float* __restrict__ starter, // [2][IDIM]
                float* __restrict__ Y)             // [b][t][j]
{
    extern __shared__ float sm[];
    float* h0s = sm;                    // [b][i]: b*1024 + i   (holds h0(t-1))
    float* h1s = sm + IDIM * 8;         //                      (holds h1(t-2))
    float* pf  = sm + IDIM * 16;        // A partials: [warp][32]; B partials at +256

    int tid  = threadIdx.x;
    int lane = tid & 31;
    int warp = tid >> 5;
    int row0 = blockIdx.x * 8;

    // ---- A-part mapping (Whh0 on h0prev, Whh1 on h1prev2): warp = mat + 2*g + 4*kc ----
    int matA = warp & 1;
    int gA   = (warp >> 1) & 1;
    int kcA  = warp >> 2;               // 0..1, K-chunk of 512
    const float* WA = matA ? Whh1 : Whh0;
    float* hA = matA ? h1s : h0s;
    int kbA = kcA * 512;
    float4 wAreg[4][4];
#pragma unroll
    for (int grp = 0; grp < 4; grp++)
#pragma unroll
        for (int r = 0; r < 4; r++)
            wAreg[grp][r] = *(const float4*)&WA[(size_t)(row0 + gA * 4 + r) * IDIM
                                                + kbA + grp * 128 + lane * 4];

    // ---- B-part mapping (Wih1 on h0prev): warp = g + 2*kc ----
    int gB  = warp & 1;
    int kcB = warp >> 1;                // 0..3, K-chunk of 256
    int kbB = kcB * 256;
    float4 wBreg[2][4];
#pragma unroll
    for (int grp = 0; grp < 2; grp++)
#pragma unroll
        for (int r = 0; r < 4; r++)
            wBreg[grp][r] = *(const float4*)&Wih1[(size_t)(row0 + gB * 4 + r) * IDIM
                                                  + kbB + grp * 128 + lane * 4];

    // combine-thread params
    // tid<64: h0 combine/U0-prefetch: b = tid&7, jl = tid>>3, j = row0+jl
    int cmb_b  = tid & 7;
    int cmb_jl = (tid & 63) >> 3;
    int cmb_j  = row0 + cmb_jl;
    float cbias = 0.0f;
    if (tid >= 64 && tid < 128) cbias = bih1[cmb_j] + bhh1[cmb_j];

    // ---- prefill exchange buffers with starter state ----
    // h0(-1) -> g_h0x[1];  h1(-1) -> g_h1x[1];  h1(-2)(unused values) -> g_h1x[0]
    if (tid < 64) {
        float s0 = starter[cmb_j];
        float s1 = starter[IDIM + cmb_j];
        g_h0x[1][cmb_b * IDIM + cmb_j] = s0;
        g_h1x[0][cmb_b * IDIM + cmb_j] = s1;
        g_h1x[1][cmb_b * IDIM + cmb_j] = s1;
    }
    unsigned epoch = 1;
    tree_sync(epoch++);

    // ================= main loop: slot t computes h0(t) and h1(t-1) =================
    for (int t = 0; t <= TLEN; t++) {
        // broadcast-in: h0(t-1) from parity (t+1)&1, h1(t-2) from parity t&1
        {
            const float4* s0 = (const float4*)g_h0x[(t + 1) & 1];
            const float4* s1 = (const float4*)g_h1x[t & 1];
            for (int v = tid; v < 2048; v += 256) {
                ((float4*)h0s)[v] = __ldcg(s0 + v);
                ((float4*)h1s)[v] = __ldcg(s1 + v);
            }
        }
        __syncthreads();

        // U0 prefetch for h0(t) (hidden under the dots)
        float u0v = 0.0f;
        if (tid < 64 && t < TLEN)
            u0v = __ldcg(&U0[(size_t)t * (BATCH * IDIM) + (size_t)cmb_b * IDIM + cmb_j]);

        // ---------- A dots: {Whh0 h0prev | Whh1 h1prev2}, 4 rows x 8 b x K512 ----------
        {
            float acc[4][8];
#pragma unroll
            for (int r = 0; r < 4; r++)
#pragma unroll
                for (int b = 0; b < 8; b++) acc[r][b] = 0.0f;
#pragma unroll
            for (int grp = 0; grp < 4; grp++) {
                int ib = kbA + grp * 128 + lane * 4;
                float4 h[8];
#pragma unroll
                for (int b = 0; b < 8; b++) h[b] = *(const float4*)&hA[b * 1024 + ib];
#pragma unroll
                for (int r = 0; r < 4; r++) {
                    float4 wv = wAreg[grp][r];
#pragma unroll
                    for (int b = 0; b < 8; b++) {
                        acc[r][b] += wv.x * h[b].x;
                        acc[r][b] += wv.y * h[b].y;
                        acc[r][b] += wv.z * h[b].z;
                        acc[r][b] += wv.w * h[b].w;
                    }
                }
            }
            reduce32_store(acc, &pf[warp * 32], lane);
        }

        // ---------- B dots: Wih1 h0prev, 4 rows x 8 b x K256 ----------
        {
            float acc[4][8];
#pragma unroll
            for (int r = 0; r < 4; r++)
#pragma unroll
                for (int b = 0; b < 8; b++) acc[r][b] = 0.0f;
#pragma unroll
            for (int grp = 0; grp < 2; grp++) {
                int ib = kbB + grp * 128 + lane * 4;
                float4 h[8];
#pragma unroll
                for (int b = 0; b < 8; b++) h[b] = *(const float4*)&h0s[b * 1024 + ib];
#pragma unroll
                for (int r = 0; r < 4; r++) {
                    float4 wv = wBreg[grp][r];
#pragma unroll
                    for (int b = 0; b < 8; b++) {
                        acc[r][b] += wv.x * h[b].x;
                        acc[r][b] += wv.y * h[b].y;
                        acc[r][b] += wv.z * h[b].z;
                        acc[r][b] += wv.w * h[b].w;
                    }
                }
            }
            reduce32_store(acc, &pf[256 + warp * 32], lane);
        }
        __syncthreads();

        // ---------- combine ----------
        if (tid < 64) {
            // h0(t) = tanh(u0(t) + Whh0 h0(t-1))
            if (t < TLEN) {
                int g = cmb_jl >> 2, r = cmb_jl & 3;
                int fidx = r * 8 + cmb_b;
                float s = pf[(0 + 2 * g) * 32 + fidx] + pf[(0 + 2 * g + 4) * 32 + fidx];
                float hv = tanhf(u0v + s);
                g_h0x[t & 1][cmb_b * IDIM + cmb_j] = hv;
            }
        } else if (tid < 128) {
            // h1(t-1) = tanh(Whh1 h1(t-2) + Wih1 h0(t-1) + biases)
            if (t >= 1) {
                int g = cmb_jl >> 2, r = cmb_jl & 3;
                int fidx = r * 8 + cmb_b;
                float sA = pf[(1 + 2 * g) * 32 + fidx] + pf[(1 + 2 * g + 4) * 32 + fidx];
                float sB = pf[256 + (g + 0) * 32 + fidx] + pf[256 + (g + 2) * 32 + fidx]
                         + pf[256 + (g + 4) * 32 + fidx] + pf[256 + (g + 6) * 32 + fidx];
                float hv = tanhf(sA + sB + cbias);
                g_h1x[(t + 1) & 1][cmb_b * IDIM + cmb_j] = hv;
                Y[((size_t)cmb_b * TLEN + (t - 1)) * IDIM + cmb_j] = hv;
            }
        }

        tree_sync(epoch++);
    }
}

// ---------------- launch ----------------
extern "C" void kernel_launch(void* const* d_in, const int* in_sizes, int n_in,
                              void* d_out, int out_size)
{
    const float* x      = (const float*)d_in[0];
    const float* w_dw0  = (const float*)d_in[1];
    const float* b_dw0  = (const float*)d_in[2];
    const float* w_dw1  = (const float*)d_in[3];
    const float* b_dw1  = (const float*)d_in[4];
    const float* w_join = (const float*)d_in[5];
    const float* b_join = (const float*)d_in[6];
    const float* w_ih0  = (const float*)d_in[7];
    const float* w_hh0  = (const float*)d_in[8];
    const float* b_ih0  = (const float*)d_in[9];
    const float* b_hh0  = (const float*)d_in[10];
    const float* w_ih1  = (const float*)d_in[11];
    const float* w_hh1  = (const float*)d_in[12];
    const float* b_ih1  = (const float*)d_in[13];
    const float* b_hh1  = (const float*)d_in[14];
    const float* w_u1   = (const float*)d_in[15];
    const float* b_u1   = (const float*)d_in[16];
    const float* w_u2   = (const float*)d_in[17];
    const float* b_u2   = (const float*)d_in[18];
    const float* starter= (const float*)d_in[19];
    float* out = (float*)d_out;

    float *H, *Z, *U0, *Yr, *Y2, *Y3;
    cudaGetSymbolAddress((void**)&H,  g_H);
    cudaGetSymbolAddress((void**)&Z,  g_Z);
    cudaGetSymbolAddress((void**)&U0, g_U0);
    cudaGetSymbolAddress((void**)&Yr, g_Yr);
    cudaGetSymbolAddress((void**)&Y2, g_Y2);
    cudaGetSymbolAddress((void**)&Y3, g_Y3);

    // 0) reset RNN tree-barrier counters (graph replays reuse device globals)
    zero_tree_kernel<<<1, 512>>>();

    // 1) dwconv0 + gelu -> H [b][d][t]
    dwconv_kernel<<<BATCH * DIMC, 256>>>(x, w_dw0, b_dw0, nullptr, H, 1);

    // 2) join: Z[b][t][i] = H[b][:,t] . w_join[i,:] + b_join
    sgemm_kernel<true, false, false><<<dim3(IDIM / BN, TLEN / BM, BATCH), 256>>>(
        H, w_join, b_join, nullptr, Z,
        TLEN, IDIM, DIMC, TLEN, (long)DIMC * TLEN, (long)TLEN * IDIM, IDIM);

    // 3) u0: U0[t][b][j] = Z[b][t][:] . w_ih0[j,:] + b_ih0 + b_hh0
    sgemm_kernel<false, false, false><<<dim3(IDIM / BN, TLEN / BM, BATCH), 256>>>(
        Z, w_ih0, b_ih0, b_hh0, U0,
        TLEN, IDIM, IDIM, IDIM, (long)TLEN * IDIM, (long)IDIM, BATCH * IDIM);

    // 4) persistent RNN over T steps -> Yr [b][t][j]
    cudaFuncSetAttribute(rnn_kernel, cudaFuncAttributeMaxDynamicSharedMemorySize,
                         RNN_SMEM_FLOATS * (int)sizeof(float));
    rnn_kernel<<<NC, 256, RNN_SMEM_FLOATS * (int)sizeof(float)>>>(
        U0, w_hh0, w_ih1, w_hh1, b_ih1, b_hh1, starter, Yr);

    // 5) u1 + gelu
    sgemm_kernel<false, true, false><<<dim3(IDIM / BN, TLEN / BM, BATCH), 256>>>(
        Yr, w_u1, b_u1, nullptr, Y2,
        TLEN, IDIM, IDIM, IDIM, (long)TLEN * IDIM, (long)TLEN * IDIM, IDIM);

    // 6) u2 + gelu, transposed store: Y3[b][d][t]
    sgemm_kernel<false, true, true><<<dim3(DIMC / BN, TLEN / BM, BATCH), 256>>>(
        Y2, w_u2, b_u2, nullptr, Y3,
        TLEN, DIMC, IDIM, IDIM, (long)TLEN * IDIM, (long)DIMC * TLEN, TLEN);

    // 7) dwconv1 + bias + residual -> out [b][d][t]
    dwconv_kernel<<<BATCH * DIMC, 256>>>(Y3, w_dw1, b_dw1, x, out, 0);
}

// round 9
// speedup vs baseline: 2.1597x; 1.2695x over previous
#include <cuda_runtime.h>
#include <math.h>
#include <stdint.h>

#define DIMC 512
#define IDIM 1024
#define BATCH 8
#define TLEN 1024
#define NC 128            // RNN CTAs (8 leaves x 16)

typedef unsigned long long u64;

// ---------------- scratch (device globals; no allocation allowed) ----------------
__device__ float g_H [BATCH*DIMC*TLEN];   // conv0+gelu out   [b][d][t]
__device__ float g_Z [BATCH*TLEN*IDIM];   // join out         [b][t][i]
__device__ float g_U0[TLEN*BATCH*IDIM];   // u0 (+b_ih0+b_hh0)[t][b][j]
__device__ float g_Yr[BATCH*TLEN*IDIM];   // rnn out          [b][t][j]
__device__ float g_Y2[BATCH*TLEN*IDIM];   // u1 out           [b][t][i]
__device__ float g_Y3[BATCH*DIMC*TLEN];   // u2 out           [b][d][t]
__device__ float g_h0x[2][BATCH*IDIM];    // h0 exchange, double buffered [b][i]
__device__ float g_h1x[2][BATCH*IDIM];    // h1 exchange, double buffered [b][i]
__device__ unsigned g_l1[8*64];           // tree-barrier leaf counters (256B apart)
__device__ unsigned g_root;               // tree-barrier root counter
__device__ volatile unsigned g_gen2;      // completed-epoch generation (monotonic)

// ---------------- packed f32x2 helpers (GEMMs only; bitwise == 2 scalar FFMAs) ----
#define FFMA2(d,a,b) asm("fma.rn.f32x2 %0, %1, %2, %0;" : "+l"(d) : "l"(a), "l"(b))

__device__ __forceinline__ u64 dup2(float x) {
    u64 d; unsigned xi = __float_as_uint(x);
    asm("mov.b64 %0, {%1, %1};" : "=l"(d) : "r"(xi));
    return d;
}
__device__ __forceinline__ void unpack2(u64 v, float& lo, float& hi) {
    unsigned a, b;
    asm("mov.b64 {%0, %1}, %2;" : "=r"(a), "=r"(b) : "l"(v));
    lo = __uint_as_float(a); hi = __uint_as_float(b);
}

// ---------------- cp.async helpers ----------------
__device__ __forceinline__ void cp_async16(uint32_t saddr, const void* gptr) {
    asm volatile("cp.async.cg.shared.global [%0], [%1], 16;" :: "r"(saddr), "l"(gptr));
}
#define CP_COMMIT() asm volatile("cp.async.commit_group;" ::: "memory")
#define CP_WAIT1()  asm volatile("cp.async.wait_group 1;" ::: "memory")
#define CP_WAIT0()  asm volatile("cp.async.wait_group 0;" ::: "memory")

__device__ __forceinline__ float gelu_f(float x) {
    return 0.5f * x * (1.0f + erff(x * 0.7071067811865476f));
}

// ---------------- barrier counter reset (graph replays reuse device globals) -----
__global__ void zero_tree_kernel() {
    int i = threadIdx.x;
    if (i < 8 * 64) g_l1[i] = 0;
    if (i == 0) { g_root = 0; g_gen2 = 0; }
}

// ---------------- depthwise conv (7 tap, pad 3) + optional gelu/residual ----------------
__global__ void dwconv_kernel(const float* __restrict__ in, const float* __restrict__ w,
                              const float* __restrict__ bias, const float* __restrict__ resid,
                              float* __restrict__ out, int do_gelu)
{
    int bd = blockIdx.x;            // b*DIMC + d
    int d  = bd % DIMC;
    __shared__ float s[TLEN + 6];
    const float* row = in + (size_t)bd * TLEN;
    for (int t = threadIdx.x; t < TLEN; t += blockDim.x) s[t + 3] = row[t];
    if (threadIdx.x < 3) { s[threadIdx.x] = 0.0f; s[TLEN + 3 + threadIdx.x] = 0.0f; }
    __syncthreads();
    float wr[7];
#pragma unroll
    for (int k = 0; k < 7; k++) wr[k] = w[d * 7 + k];
    float bb = bias[d];
    for (int t = threadIdx.x; t < TLEN; t += blockDim.x) {
        float acc = bb;
#pragma unroll
        for (int k = 0; k < 7; k++) acc += s[t + k] * wr[k];
        if (do_gelu) acc = gelu_f(acc);
        if (resid)   acc += resid[(size_t)bd * TLEN + t];
        out[(size_t)bd * TLEN + t] = acc;
    }
}

// ---------------- tiled SGEMM, f32x2 packed inner loop (bitwise == scalar) -------
#define BM 128
#define BN 64
#define BK 16

template<bool A_COL, bool DO_GELU, bool STORE_T>
__global__ __launch_bounds__(256)
void sgemm_kernel(const float* __restrict__ A, const float* __restrict__ B,
                  const float* __restrict__ bias, const float* __restrict__ bias2,
                  float* __restrict__ C,
                  int M, int N, int K, int lda,
                  long strideA, long strideC, int ldc)
{
    A += (long)blockIdx.z * strideA;
    C += (long)blockIdx.z * strideC;
    int m0 = blockIdx.y * BM;
    int n0 = blockIdx.x * BN;

    __shared__ float As[BK][BM + 4];
    __shared__ float Bs[BK][BN + 4];

    int tid = threadIdx.x;
    int tx = tid & 15;
    int ty = tid >> 4;

    u64 acc2[4][4];
#pragma unroll
    for (int i = 0; i < 4; i++)
#pragma unroll
        for (int j = 0; j < 4; j++) acc2[i][j] = 0ULL;

    for (int k0 = 0; k0 < K; k0 += BK) {
        if (A_COL) {
            int kk = tid >> 4;
            int mm = (tid & 15) * 8;
            const float4* src = (const float4*)(A + (size_t)(k0 + kk) * lda + m0 + mm);
            float4 v0 = src[0], v1 = src[1];
            *(float4*)&As[kk][mm]     = v0;
            *(float4*)&As[kk][mm + 4] = v1;
        } else {
            int mm = tid >> 1;
            int kk = (tid & 1) * 8;
            const float4* src = (const float4*)(A + (size_t)(m0 + mm) * lda + k0 + kk);
            float4 v0 = src[0], v1 = src[1];
            As[kk + 0][mm] = v0.x; As[kk + 1][mm] = v0.y; As[kk + 2][mm] = v0.z; As[kk + 3][mm] = v0.w;
            As[kk + 4][mm] = v1.x; As[kk + 5][mm] = v1.y; As[kk + 6][mm] = v1.z; As[kk + 7][mm] = v1.w;
        }
        {
            int nn = tid >> 2;
            int kk = (tid & 3) * 4;
            float4 v = *(const float4*)(B + (size_t)(n0 + nn) * K + k0 + kk);
            Bs[kk + 0][nn] = v.x; Bs[kk + 1][nn] = v.y; Bs[kk + 2][nn] = v.z; Bs[kk + 3][nn] = v.w;
        }
        __syncthreads();

#pragma unroll
        for (int k = 0; k < BK; k++) {
            ulonglong2 p0 = *(const ulonglong2*)&As[k][ty * 8];
            ulonglong2 p1 = *(const ulonglong2*)&As[k][ty * 8 + 4];
            u64 ap[4] = {p0.x, p0.y, p1.x, p1.y};
            float4 b0 = *(const float4*)&Bs[k][tx * 4];
            u64 bd[4] = {dup2(b0.x), dup2(b0.y), dup2(b0.z), dup2(b0.w)};
#pragma unroll
            for (int i = 0; i < 4; i++)
#pragma unroll
                for (int j = 0; j < 4; j++) FFMA2(acc2[i][j], ap[i], bd[j]);
        }
        __syncthreads();
    }

#pragma unroll
    for (int j = 0; j < 4; j++) {
        int n = n0 + tx * 4 + j;
        float bv = bias[n];
        if (bias2) bv += bias2[n];
#pragma unroll
        for (int i = 0; i < 4; i++) {
            float vlo, vhi;
            unpack2(acc2[i][j], vlo, vhi);
            int m = m0 + ty * 8 + 2 * i;
            float a = vlo + bv, b = vhi + bv;
            if (DO_GELU) { a = gelu_f(a); b = gelu_f(b); }
            if (STORE_T) { C[(size_t)n * ldc + m] = a; C[(size_t)n * ldc + m + 1] = b; }
            else         { C[(size_t)m * ldc + n] = a; C[(size_t)(m + 1) * ldc + n] = b; }
        }
    }
}

// ---------------- persistent RNN kernel: pipelined single-sync-per-slot ----------------
// smem: h0s[8192] + h1s[8192] ([b][i]) + pf[512] (A partials at 0, B partials at 256)
#define RNN_SMEM_FLOATS (IDIM*16 + 512)

// tree barrier, monotonic counters, epoch e >= 1
__device__ __forceinline__ void tree_sync(unsigned e)
{
    __syncthreads();
    if (threadIdx.x == 0) {
        __threadfence();
        unsigned grp = blockIdx.x & 7;               // 16 CTAs per leaf
        if (atomicAdd(&g_l1[grp * 64], 1u) == 16u * e - 1u) {
            if (atomicAdd(&g_root, 1u) == 8u * e - 1u) {
                __threadfence();
                g_gen2 = e;
            }
        }
        while (g_gen2 < e) { }
        __threadfence();
    }
    __syncthreads();
}

// recursive-halving butterfly: input a[32] (value id v = index), output: full 32-lane
// sum of value id == lane, returned. Masks 16,8,4,2,1 with position compaction.
__device__ __forceinline__ float bfly_reduce32(float* a, int lane) {
#pragma unroll
    for (int p = 0; p < 16; p++) {
        bool up = (lane & 16) != 0;
        float send = up ? a[p] : a[p + 16];
        float keep = up ? a[p + 16] : a[p];
        a[p] = keep + __shfl_xor_sync(0xffffffffu, send, 16);
    }
#pragma unroll
    for (int p = 0; p < 8; p++) {
        bool up = (lane & 8) != 0;
        float send = up ? a[p] : a[p + 8];
        float keep = up ? a[p + 8] : a[p];
        a[p] = keep + __shfl_xor_sync(0xffffffffu, send, 8);
    }
#pragma unroll
    for (int p = 0; p < 4; p++) {
        bool up = (lane & 4) != 0;
        float send = up ? a[p] : a[p + 4];
        float keep = up ? a[p + 4] : a[p];
        a[p] = keep + __shfl_xor_sync(0xffffffffu, send, 4);
    }
#pragma unroll
    for (int p = 0; p < 2; p++) {
        bool up = (lane & 2) != 0;
        float send = up ? a[p] : a[p + 2];
        float keep = up ? a[p + 2] : a[p];
        a[p] = keep + __shfl_xor_sync(0xffffffffu, send, 2);
    }
    {
        bool up = (lane & 1) != 0;
        float send = up ? a[0] : a[1];
        float keep = up ? a[1] : a[0];
        a[0] = keep + __shfl_xor_sync(0xffffffffu, send, 1);
    }
    return a[0];
}

__global__ __launch_bounds__(256, 1)
void rnn_kernel(const float* __restrict__ U0,     // [t][b][j], includes b_ih0+b_hh0
                const float* __restrict__ Whh0,
                const float* __restrict__ Wih1,
                const float* __restrict__ Whh1,
                const float* __restrict__ bih1,
                const float* __restrict__ bhh1,
                const float* __restrict__ starter, // [2][IDIM]
                float* __restrict__ Y)             // [b][t][j]
{
    extern __shared__ float sm[];
    float* h0s = sm;                    // [b][i]: b*1024 + i   (holds h0(t-1))
    float* h1s = sm + IDIM * 8;         //                      (holds h1(t-2))
    float* pf  = sm + IDIM * 16;        // A partials [warp][32]; B partials at +256

    int tid  = threadIdx.x;
    int lane = tid & 31;
    int warp = tid >> 5;
    int row0 = blockIdx.x * 8;

    uint32_t h0sa = (uint32_t)__cvta_generic_to_shared(h0s);
    uint32_t h1sa = (uint32_t)__cvta_generic_to_shared(h1s);

    // ---- A-part mapping (Whh0 on h0prev, Whh1 on h1prev2): warp = mat + 2*g + 4*kc ----
    int matA = warp & 1;
    int gA   = (warp >> 1) & 1;
    int kcA  = warp >> 2;               // 0..1, K-chunk of 512
    const float* WA = matA ? Whh1 : Whh0;
    float* hA = matA ? h1s : h0s;
    int kbA = kcA * 512;
    float4 wAreg[4][4];
#pragma unroll
    for (int grp = 0; grp < 4; grp++)
#pragma unroll
        for (int r = 0; r < 4; r++)
            wAreg[grp][r] = *(const float4*)&WA[(size_t)(row0 + gA * 4 + r) * IDIM
                                                + kbA + grp * 128 + lane * 4];

    // ---- B-part mapping (Wih1 on h0prev): warp = g + 2*kc ----
    int gB  = warp & 1;
    int kcB = warp >> 1;                // 0..3, K-chunk of 256
    int kbB = kcB * 256;
    float4 wBreg[2][4];
#pragma unroll
    for (int grp = 0; grp < 2; grp++)
#pragma unroll
        for (int r = 0; r < 4; r++)
            wBreg[grp][r] = *(const float4*)&Wih1[(size_t)(row0 + gB * 4 + r) * IDIM
                                                  + kbB + grp * 128 + lane * 4];

    // combine-thread params: b = tid&7, jl = (tid&63)>>3, j = row0+jl
    int cmb_b  = tid & 7;
    int cmb_jl = (tid & 63) >> 3;
    int cmb_j  = row0 + cmb_jl;
    float cbias = 0.0f;
    if (tid >= 64 && tid < 128) cbias = bih1[cmb_j] + bhh1[cmb_j];

    // ---- prefill exchange buffers with starter state ----
    if (tid < 64) {
        float s0 = starter[cmb_j];
        float s1 = starter[IDIM + cmb_j];
        g_h0x[1][cmb_b * IDIM + cmb_j] = s0;
        g_h1x[0][cmb_b * IDIM + cmb_j] = s1;
        g_h1x[1][cmb_b * IDIM + cmb_j] = s1;
    }
    unsigned epoch = 1;
    tree_sync(epoch++);

    // ================= main loop: slot t computes h0(t) and h1(t-1) =================
    for (int t = 0; t <= TLEN; t++) {
        // async broadcast-in: h0(t-1) [group 0], h1(t-2) [group 1]
        {
            const float4* s0 = (const float4*)g_h0x[(t + 1) & 1];
            const float4* s1 = (const float4*)g_h1x[t & 1];
#pragma unroll
            for (int q = 0; q < 8; q++)
                cp_async16(h0sa + (unsigned)(tid + q * 256) * 16u, s0 + tid + q * 256);
            CP_COMMIT();
#pragma unroll
            for (int q = 0; q < 8; q++)
                cp_async16(h1sa + (unsigned)(tid + q * 256) * 16u, s1 + tid + q * 256);
            CP_COMMIT();
        }

        // U0 prefetch for h0(t) (hidden under the dots)
        float u0v = 0.0f;
        if (tid < 64 && t < TLEN)
            u0v = __ldcg(&U0[(size_t)t * (BATCH * IDIM) + (size_t)cmb_b * IDIM + cmb_j]);

        CP_WAIT1();             // h0 group done (h1 still in flight)
        __syncthreads();

        // ---------- B dots first (need only h0): Wih1 h0prev, 4r x 8b x K256 --------
        {
            float acc[32];
#pragma unroll
            for (int v = 0; v < 32; v++) acc[v] = 0.0f;
#pragma unroll
            for (int grp = 0; grp < 2; grp++) {
                int ib = kbB + grp * 128 + lane * 4;
                float4 h[8];
#pragma unroll
                for (int b = 0; b < 8; b++) h[b] = *(const float4*)&h0s[b * 1024 + ib];
#pragma unroll
                for (int r = 0; r < 4; r++) {
                    float4 wv = wBreg[grp][r];
#pragma unroll
                    for (int b = 0; b < 8; b++) {
                        acc[r * 8 + b] += wv.x * h[b].x;
                        acc[r * 8 + b] += wv.y * h[b].y;
                        acc[r * 8 + b] += wv.z * h[b].z;
                        acc[r * 8 + b] += wv.w * h[b].w;
                    }
                }
            }
            pf[256 + warp * 32 + lane] = bfly_reduce32(acc, lane);
        }

        CP_WAIT0();             // h1 group done
        __syncthreads();

        // ---------- A dots: {Whh0 h0prev | Whh1 h1prev2}, 4r x 8b x K512 ----------
        {
            float acc[32];
#pragma unroll
            for (int v = 0; v < 32; v++) acc[v] = 0.0f;
#pragma unroll
            for (int grp = 0; grp < 4; grp++) {
                int ib = kbA + grp * 128 + lane * 4;
                float4 h[8];
#pragma unroll
                for (int b = 0; b < 8; b++) h[b] = *(const float4*)&hA[b * 1024 + ib];
#pragma unroll
                for (int r = 0; r < 4; r++) {
                    float4 wv = wAreg[grp][r];
#pragma unroll
                    for (int b = 0; b < 8; b++) {
                        acc[r * 8 + b] += wv.x * h[b].x;
                        acc[r * 8 + b] += wv.y * h[b].y;
                        acc[r * 8 + b] += wv.z * h[b].z;
                        acc[r * 8 + b] += wv.w * h[b].w;
                    }
                }
            }
            pf[warp * 32 + lane] = bfly_reduce32(acc, lane);
        }
        __syncthreads();

        // ---------- combine ----------
        if (tid < 64) {
            // h0(t) = tanh(u0(t) + Whh0 h0(t-1))
            if (t < TLEN) {
                int g = cmb_jl >> 2, r = cmb_jl & 3;
                int fidx = r * 8 + cmb_b;
                float s = pf[(0 + 2 * g) * 32 + fidx] + pf[(0 + 2 * g + 4) * 32 + fidx];
                float hv = tanhf(u0v + s);
                g_h0x[t & 1][cmb_b * IDIM + cmb_j] = hv;
            }
        } else if (tid < 128) {
            // h1(t-1) = tanh(Whh1 h1(t-2) + Wih1 h0(t-1) + biases)
            if (t >= 1) {
                int g = cmb_jl >> 2, r = cmb_jl & 3;
                int fidx = r * 8 + cmb_b;
                float sA = pf[(1 + 2 * g) * 32 + fidx] + pf[(1 + 2 * g + 4) * 32 + fidx];
                float sB = pf[256 + (g + 0) * 32 + fidx] + pf[256 + (g + 2) * 32 + fidx]
                         + pf[256 + (g + 4) * 32 + fidx] + pf[256 + (g + 6) * 32 + fidx];
                float hv = tanhf(sA + sB + cbias);
                g_h1x[(t + 1) & 1][cmb_b * IDIM + cmb_j] = hv;
                Y[((size_t)cmb_b * TLEN + (t - 1)) * IDIM + cmb_j] = hv;
            }
        }

        tree_sync(epoch++);
    }
}

// ---------------- launch ----------------
extern "C" void kernel_launch(void* const* d_in, const int* in_sizes, int n_in,
                              void* d_out, int out_size)
{
    const float* x      = (const float*)d_in[0];
    const float* w_dw0  = (const float*)d_in[1];
    const float* b_dw0  = (const float*)d_in[2];
    const float* w_dw1  = (const float*)d_in[3];
    const float* b_dw1  = (const float*)d_in[4];
    const float* w_join = (const float*)d_in[5];
    const float* b_join = (const float*)d_in[6];
    const float* w_ih0  = (const float*)d_in[7];
    const float* w_hh0  = (const float*)d_in[8];
    const float* b_ih0  = (const float*)d_in[9];
    const float* b_hh0  = (const float*)d_in[10];
    const float* w_ih1  = (const float*)d_in[11];
    const float* w_hh1  = (const float*)d_in[12];
    const float* b_ih1  = (const float*)d_in[13];
    const float* b_hh1  = (const float*)d_in[14];
    const float* w_u1   = (const float*)d_in[15];
    const float* b_u1   = (const float*)d_in[16];
    const float* w_u2   = (const float*)d_in[17];
    const float* b_u2   = (const float*)d_in[18];
    const float* starter= (const float*)d_in[19];
    float* out = (float*)d_out;

    float *H, *Z, *U0, *Yr, *Y2, *Y3;
    cudaGetSymbolAddress((void**)&H,  g_H);
    cudaGetSymbolAddress((void**)&Z,  g_Z);
    cudaGetSymbolAddress((void**)&U0, g_U0);
    cudaGetSymbolAddress((void**)&Yr, g_Yr);
    cudaGetSymbolAddress((void**)&Y2, g_Y2);
    cudaGetSymbolAddress((void**)&Y3, g_Y3);

    // 0) reset RNN tree-barrier counters (graph replays reuse device globals)
    zero_tree_kernel<<<1, 512>>>();

    // 1) dwconv0 + gelu -> H [b][d][t]
    dwconv_kernel<<<BATCH * DIMC, 256>>>(x, w_dw0, b_dw0, nullptr, H, 1);

    // 2) join: Z[b][t][i] = H[b][:,t] . w_join[i,:] + b_join
    sgemm_kernel<true, false, false><<<dim3(IDIM / BN, TLEN / BM, BATCH), 256>>>(
        H, w_join, b_join, nullptr, Z,
        TLEN, IDIM, DIMC, TLEN, (long)DIMC * TLEN, (long)TLEN * IDIM, IDIM);

    // 3) u0: U0[t][b][j] = Z[b][t][:] . w_ih0[j,:] + b_ih0 + b_hh0
    sgemm_kernel<false, false, false><<<dim3(IDIM / BN, TLEN / BM, BATCH), 256>>>(
        Z, w_ih0, b_ih0, b_hh0, U0,
        TLEN, IDIM, IDIM, IDIM, (long)TLEN * IDIM, (long)IDIM, BATCH * IDIM);

    // 4) persistent RNN over T steps -> Yr [b][t][j]
    cudaFuncSetAttribute(rnn_kernel, cudaFuncAttributeMaxDynamicSharedMemorySize,
                         RNN_SMEM_FLOATS * (int)sizeof(float));
    rnn_kernel<<<NC, 256, RNN_SMEM_FLOATS * (int)sizeof(float)>>>(
        U0, w_hh0, w_ih1, w_hh1, b_ih1, b_hh1, starter, Yr);

    // 5) u1 + gelu
    sgemm_kernel<false, true, false><<<dim3(IDIM / BN, TLEN / BM, BATCH), 256>>>(
        Yr, w_u1, b_u1, nullptr, Y2,
        TLEN, IDIM, IDIM, IDIM, (long)TLEN * IDIM, (long)TLEN * IDIM, IDIM);

    // 6) u2 + gelu, transposed store: Y3[b][d][t]
    sgemm_kernel<false, true, true><<<dim3(DIMC / BN, TLEN / BM, BATCH), 256>>>(
        Y2, w_u2, b_u2, nullptr, Y3,
        TLEN, DIMC, IDIM, IDIM, (long)TLEN * IDIM, (long)DIMC * TLEN, TLEN);

    // 7) dwconv1 + bias + residual -> out [b][d][t]
    dwconv_kernel<<<BATCH * DIMC, 256>>>(Y3, w_dw1, b_dw1, x, out, 0);
}